// round 3
// baseline (speedup 1.0000x reference)
#include <cuda_runtime.h>
#include <math.h>

#define BATCH 4
#define SEQ   4096
#define EMB   1024
#define DIM   128

// Scratch for projected Q, K, V (no cudaMalloc allowed)
__device__ float g_Q[BATCH * SEQ * DIM];
__device__ float g_K[BATCH * SEQ * DIM];
__device__ float g_V[BATCH * SEQ * DIM];

// ---------------------------------------------------------------------------
// Kernel 1: fused QKV projection.  C[16384, 128] = x[16384,1024] @ W[1024,128]
// blockIdx.y selects which W / which destination.  BM=128, BN=128, BK=8,
// 256 threads, 8x8 register tile per thread.
// ---------------------------------------------------------------------------
__global__ __launch_bounds__(256) void proj_kernel(
    const float* __restrict__ x,
    const float* __restrict__ Wq,
    const float* __restrict__ Wk,
    const float* __restrict__ Wv)
{
    __shared__ float As[8 * 128];   // As[k][m]  (transposed A tile)
    __shared__ float Bs[8 * 128];   // Bs[k][n]

    const int m0    = blockIdx.x * 128;
    const int which = blockIdx.y;
    const float* W  = (which == 0) ? Wq : (which == 1) ? Wk : Wv;
    float* dst      = (which == 0) ? g_Q : (which == 1) ? g_K : g_V;

    const int tid = threadIdx.x;
    const int ty  = tid >> 4;          // 0..15 -> rows ty*8 .. ty*8+7
    const int tx  = tid & 15;          // 0..15 -> cols tx*8 .. tx*8+7

    // A-tile load indices: 2 threads per m-row, each loads a float4 of k
    const int la_m = tid >> 1;             // 0..127
    const int la_k = (tid & 1) * 4;        // 0 or 4
    // B-tile load indices: 1 warp per k-row
    const int lb_k = tid >> 5;             // 0..7
    const int lb_n = (tid & 31) * 4;       // 0..124

    float acc[8][8];
#pragma unroll
    for (int i = 0; i < 8; i++)
#pragma unroll
        for (int j = 0; j < 8; j++) acc[i][j] = 0.0f;

    for (int k0 = 0; k0 < EMB; k0 += 8) {
        float4 av = *(const float4*)(x + (size_t)(m0 + la_m) * EMB + k0 + la_k);
        As[(la_k + 0) * 128 + la_m] = av.x;
        As[(la_k + 1) * 128 + la_m] = av.y;
        As[(la_k + 2) * 128 + la_m] = av.z;
        As[(la_k + 3) * 128 + la_m] = av.w;
        *(float4*)(Bs + lb_k * 128 + lb_n) =
            *(const float4*)(W + (size_t)(k0 + lb_k) * DIM + lb_n);
        __syncthreads();

#pragma unroll
        for (int k = 0; k < 8; k++) {
            float4 a0 = *(const float4*)(As + k * 128 + ty * 8);
            float4 a1 = *(const float4*)(As + k * 128 + ty * 8 + 4);
            float4 b0 = *(const float4*)(Bs + k * 128 + tx * 8);
            float4 b1 = *(const float4*)(Bs + k * 128 + tx * 8 + 4);
            float a[8] = {a0.x, a0.y, a0.z, a0.w, a1.x, a1.y, a1.z, a1.w};
            float b[8] = {b0.x, b0.y, b0.z, b0.w, b1.x, b1.y, b1.z, b1.w};
#pragma unroll
            for (int i = 0; i < 8; i++)
#pragma unroll
                for (int j = 0; j < 8; j++)
                    acc[i][j] = fmaf(a[i], b[j], acc[i][j]);
        }
        __syncthreads();
    }

#pragma unroll
    for (int i = 0; i < 8; i++) {
        float* p = dst + (size_t)(m0 + ty * 8 + i) * DIM + tx * 8;
        *(float4*)(p)     = make_float4(acc[i][0], acc[i][1], acc[i][2], acc[i][3]);
        *(float4*)(p + 4) = make_float4(acc[i][4], acc[i][5], acc[i][6], acc[i][7]);
    }
}

// ---------------------------------------------------------------------------
// Kernel 2: causal flash attention, fp32, online softmax.
// One block = (batch, 64-row q-tile).  256 threads.
//   S phase : thread grid 16x16, each thread computes a 4x4 block of S[64,64]
//   PV phase: same (ty,tx), each thread owns O rows ty*4..+3, cols tx*8..+7
// smem: Qt[128][64], Kt[128][64] (k-major transposed), Vs[64][128], Pt[64][68]
// ---------------------------------------------------------------------------
#define SM_QT 0
#define SM_KT 8192
#define SM_VS 16384
#define SM_PT 24576
#define SM_FLOATS (24576 + 64 * 68)   // 28928 floats = 115712 bytes

__global__ __launch_bounds__(256) void flash_kernel(float* __restrict__ out)
{
    extern __shared__ float sm[];
    float* Qt = sm + SM_QT;   // Qt[kk*64 + r]
    float* Kt = sm + SM_KT;   // Kt[kk*64 + c]
    float* Vs = sm + SM_VS;   // Vs[k*128 + c]
    float* Pt = sm + SM_PT;   // Pt[k*68 + r]

    const int bid = blockIdx.x;
    const int b   = bid & 3;
    const int qt  = 63 - (bid >> 2);     // heavy tiles first (load balance)
    const int q0  = qt * 64;

    const float* Qb = g_Q + (size_t)b * SEQ * DIM;
    const float* Kb = g_K + (size_t)b * SEQ * DIM;
    const float* Vb = g_V + (size_t)b * SEQ * DIM;
    float*       Ob = out + (size_t)b * SEQ * DIM;

    const int tid = threadIdx.x;
    const int ty  = tid >> 4;            // 0..15
    const int tx  = tid & 15;            // 0..15
    const int ty4 = ty * 4, tx4 = tx * 4, tx8 = tx * 8;

    // cooperative-load indices (transpose into smem)
    const int lr = tid >> 2;             // 0..63 (row)
    const int lk = (tid & 3) * 4;        // k base
    const int lc = (tid & 3) * 32;       // col base for V

    // ---- load Q tile transposed ----
    {
        const float* src = Qb + (size_t)(q0 + lr) * DIM;
#pragma unroll
        for (int u = 0; u < 8; u++) {
            int kk = lk + u * 16;
            float4 v = *(const float4*)(src + kk);
            Qt[(kk + 0) * 64 + lr] = v.x;
            Qt[(kk + 1) * 64 + lr] = v.y;
            Qt[(kk + 2) * 64 + lr] = v.z;
            Qt[(kk + 3) * 64 + lr] = v.w;
        }
    }

    float acc[4][8];
#pragma unroll
    for (int i = 0; i < 4; i++)
#pragma unroll
        for (int j = 0; j < 8; j++) acc[i][j] = 0.0f;
    float m_i[4], l_i[4];
#pragma unroll
    for (int i = 0; i < 4; i++) { m_i[i] = -1e30f; l_i[i] = 0.0f; }

    const float scale = 0.03125f;        // 1/sqrt(1024)

    for (int kt = 0; kt <= qt; kt++) {
        const int k0 = kt * 64;
        __syncthreads();   // protect Qt (iter 0) / Kt,Vs,Pt (later iters)

        // ---- load K tile transposed ----
        {
            const float* src = Kb + (size_t)(k0 + lr) * DIM;
#pragma unroll
            for (int u = 0; u < 8; u++) {
                int kk = lk + u * 16;
                float4 v = *(const float4*)(src + kk);
                Kt[(kk + 0) * 64 + lr] = v.x;
                Kt[(kk + 1) * 64 + lr] = v.y;
                Kt[(kk + 2) * 64 + lr] = v.z;
                Kt[(kk + 3) * 64 + lr] = v.w;
            }
        }
        // ---- load V tile row-major ----
        {
            const float* src = Vb + (size_t)(k0 + lr) * DIM + lc;
            float* dstv = Vs + lr * 128 + lc;
#pragma unroll
            for (int u = 0; u < 8; u++)
                *(float4*)(dstv + u * 4) = *(const float4*)(src + u * 4);
        }
        __syncthreads();

        // ---- S = Q K^T (4x4 per thread) ----
        float s[4][4];
#pragma unroll
        for (int i = 0; i < 4; i++)
#pragma unroll
            for (int j = 0; j < 4; j++) s[i][j] = 0.0f;

#pragma unroll 8
        for (int kk = 0; kk < 128; kk++) {
            float4 qv = *(const float4*)(Qt + kk * 64 + ty4);
            float4 kv = *(const float4*)(Kt + kk * 64 + tx4);
            float qa[4] = {qv.x, qv.y, qv.z, qv.w};
            float kb[4] = {kv.x, kv.y, kv.z, kv.w};
#pragma unroll
            for (int i = 0; i < 4; i++)
#pragma unroll
                for (int j = 0; j < 4; j++)
                    s[i][j] = fmaf(qa[i], kb[j], s[i][j]);
        }

        // ---- scale + causal mask (only on diagonal tile, k0 == q0) ----
        const bool diag = (kt == qt);
#pragma unroll
        for (int i = 0; i < 4; i++)
#pragma unroll
            for (int j = 0; j < 4; j++) {
                s[i][j] *= scale;
                if (diag && (tx4 + j) > (ty4 + i)) s[i][j] = -1e30f;
            }

        // ---- online softmax stats (rows shared by 16 tx-threads) ----
        float alpha[4];
#pragma unroll
        for (int i = 0; i < 4; i++) {
            float t = fmaxf(fmaxf(s[i][0], s[i][1]), fmaxf(s[i][2], s[i][3]));
#pragma unroll
            for (int off = 1; off < 16; off <<= 1)
                t = fmaxf(t, __shfl_xor_sync(0xffffffffu, t, off));
            float mn = fmaxf(m_i[i], t);
            alpha[i] = __expf(m_i[i] - mn);

            float r = 0.0f;
#pragma unroll
            for (int j = 0; j < 4; j++) {
                s[i][j] = __expf(s[i][j] - mn);
                r += s[i][j];
            }
#pragma unroll
            for (int off = 1; off < 16; off <<= 1)
                r += __shfl_xor_sync(0xffffffffu, r, off);

            l_i[i] = l_i[i] * alpha[i] + r;
            m_i[i] = mn;
        }

        // ---- stash P transposed: Pt[col][row] ----
#pragma unroll
        for (int i = 0; i < 4; i++)
#pragma unroll
            for (int j = 0; j < 4; j++)
                Pt[(tx4 + j) * 68 + ty4 + i] = s[i][j];
        __syncthreads();

        // ---- rescale accumulator, then O += P @ V ----
#pragma unroll
        for (int i = 0; i < 4; i++)
#pragma unroll
            for (int j = 0; j < 8; j++) acc[i][j] *= alpha[i];

#pragma unroll 4
        for (int k = 0; k < 64; k++) {
            float4 pv = *(const float4*)(Pt + k * 68 + ty4);
            float4 v0 = *(const float4*)(Vs + k * 128 + tx8);
            float4 v1 = *(const float4*)(Vs + k * 128 + tx8 + 4);
            float pp[4] = {pv.x, pv.y, pv.z, pv.w};
            float vv[8] = {v0.x, v0.y, v0.z, v0.w, v1.x, v1.y, v1.z, v1.w};
#pragma unroll
            for (int i = 0; i < 4; i++)
#pragma unroll
                for (int j = 0; j < 8; j++)
                    acc[i][j] = fmaf(pp[i], vv[j], acc[i][j]);
        }
    }

    // ---- epilogue: normalize and store ----
#pragma unroll
    for (int i = 0; i < 4; i++) {
        float inv = 1.0f / l_i[i];
        float* p = Ob + (size_t)(q0 + ty4 + i) * DIM + tx8;
        *(float4*)(p)     = make_float4(acc[i][0] * inv, acc[i][1] * inv,
                                        acc[i][2] * inv, acc[i][3] * inv);
        *(float4*)(p + 4) = make_float4(acc[i][4] * inv, acc[i][5] * inv,
                                        acc[i][6] * inv, acc[i][7] * inv);
    }
}

// ---------------------------------------------------------------------------
extern "C" void kernel_launch(void* const* d_in, const int* in_sizes, int n_in,
                              void* d_out, int out_size)
{
    const float* x  = (const float*)d_in[0];
    const float* Wq = (const float*)d_in[1];
    const float* Wk = (const float*)d_in[2];
    const float* Wv = (const float*)d_in[3];
    float* out = (float*)d_out;

    (void)in_sizes; (void)n_in; (void)out_size;

    // Stage 1: QKV projections (one pass over x per W)
    proj_kernel<<<dim3(BATCH * SEQ / 128, 3), 256>>>(x, Wq, Wk, Wv);

    // Stage 2: causal flash attention
    const size_t smem_bytes = SM_FLOATS * sizeof(float);   // 115712
    cudaFuncSetAttribute(flash_kernel,
                         cudaFuncAttributeMaxDynamicSharedMemorySize,
                         (int)smem_bytes);
    flash_kernel<<<BATCH * (SEQ / 64), 256, smem_bytes>>>(out);
}

// round 4
// speedup vs baseline: 1.0021x; 1.0021x over previous
#include <cuda_runtime.h>
#include <math.h>

#define BATCH 4
#define SEQ   4096
#define EMB   1024
#define DIM   128

// Scratch for projected Q, K, V (no cudaMalloc allowed)
__device__ float g_Q[BATCH * SEQ * DIM];
__device__ float g_K[BATCH * SEQ * DIM];
__device__ float g_V[BATCH * SEQ * DIM];

// ---------------------------------------------------------------------------
// Kernel 1: fused QKV projection.  C[16384, 128] = x[16384,1024] @ W[1024,128]
// blockIdx.y selects which W / which destination.  BM=128, BN=128, BK=8,
// 256 threads, 8x8 register tile per thread.
// ---------------------------------------------------------------------------
__global__ __launch_bounds__(256) void proj_kernel(
    const float* __restrict__ x,
    const float* __restrict__ Wq,
    const float* __restrict__ Wk,
    const float* __restrict__ Wv)
{
    __shared__ float As[8 * 128];   // As[k][m]  (transposed A tile)
    __shared__ float Bs[8 * 128];   // Bs[k][n]

    const int m0    = blockIdx.x * 128;
    const int which = blockIdx.y;
    const float* W  = (which == 0) ? Wq : (which == 1) ? Wk : Wv;
    float* dst      = (which == 0) ? g_Q : (which == 1) ? g_K : g_V;

    const int tid = threadIdx.x;
    const int ty  = tid >> 4;          // 0..15 -> rows ty*8 .. ty*8+7
    const int tx  = tid & 15;          // 0..15 -> cols tx*8 .. tx*8+7

    // A-tile load indices: 2 threads per m-row, each loads a float4 of k
    const int la_m = tid >> 1;             // 0..127
    const int la_k = (tid & 1) * 4;        // 0 or 4
    // B-tile load indices: 1 warp per k-row
    const int lb_k = tid >> 5;             // 0..7
    const int lb_n = (tid & 31) * 4;       // 0..124

    float acc[8][8];
#pragma unroll
    for (int i = 0; i < 8; i++)
#pragma unroll
        for (int j = 0; j < 8; j++) acc[i][j] = 0.0f;

    for (int k0 = 0; k0 < EMB; k0 += 8) {
        float4 av = *(const float4*)(x + (size_t)(m0 + la_m) * EMB + k0 + la_k);
        As[(la_k + 0) * 128 + la_m] = av.x;
        As[(la_k + 1) * 128 + la_m] = av.y;
        As[(la_k + 2) * 128 + la_m] = av.z;
        As[(la_k + 3) * 128 + la_m] = av.w;
        *(float4*)(Bs + lb_k * 128 + lb_n) =
            *(const float4*)(W + (size_t)(k0 + lb_k) * DIM + lb_n);
        __syncthreads();

#pragma unroll
        for (int k = 0; k < 8; k++) {
            float4 a0 = *(const float4*)(As + k * 128 + ty * 8);
            float4 a1 = *(const float4*)(As + k * 128 + ty * 8 + 4);
            float4 b0 = *(const float4*)(Bs + k * 128 + tx * 8);
            float4 b1 = *(const float4*)(Bs + k * 128 + tx * 8 + 4);
            float a[8] = {a0.x, a0.y, a0.z, a0.w, a1.x, a1.y, a1.z, a1.w};
            float b[8] = {b0.x, b0.y, b0.z, b0.w, b1.x, b1.y, b1.z, b1.w};
#pragma unroll
            for (int i = 0; i < 8; i++)
#pragma unroll
                for (int j = 0; j < 8; j++)
                    acc[i][j] = fmaf(a[i], b[j], acc[i][j]);
        }
        __syncthreads();
    }

#pragma unroll
    for (int i = 0; i < 8; i++) {
        float* p = dst + (size_t)(m0 + ty * 8 + i) * DIM + tx * 8;
        *(float4*)(p)     = make_float4(acc[i][0], acc[i][1], acc[i][2], acc[i][3]);
        *(float4*)(p + 4) = make_float4(acc[i][4], acc[i][5], acc[i][6], acc[i][7]);
    }
}

// ---------------------------------------------------------------------------
// Kernel 2: causal flash attention, fp32, online softmax.
// One block = (batch, 64-row q-tile).  256 threads.
//   S phase : thread grid 16x16, each thread computes a 4x4 block of S[64,64]
//   PV phase: same (ty,tx), each thread owns O rows ty*4..+3, cols tx*8..+7
// smem: Qt[128][64], Kt[128][64] (k-major transposed), Vs[64][128], Pt[64][68]
// ---------------------------------------------------------------------------
#define SM_QT 0
#define SM_KT 8192
#define SM_VS 16384
#define SM_PT 24576
#define SM_FLOATS (24576 + 64 * 68)   // 28928 floats = 115712 bytes

__global__ __launch_bounds__(256) void flash_kernel(float* __restrict__ out)
{
    extern __shared__ float sm[];
    float* Qt = sm + SM_QT;   // Qt[kk*64 + r]
    float* Kt = sm + SM_KT;   // Kt[kk*64 + c]
    float* Vs = sm + SM_VS;   // Vs[k*128 + c]
    float* Pt = sm + SM_PT;   // Pt[k*68 + r]

    const int bid = blockIdx.x;
    const int b   = bid & 3;
    const int qt  = 63 - (bid >> 2);     // heavy tiles first (load balance)
    const int q0  = qt * 64;

    const float* Qb = g_Q + (size_t)b * SEQ * DIM;
    const float* Kb = g_K + (size_t)b * SEQ * DIM;
    const float* Vb = g_V + (size_t)b * SEQ * DIM;
    float*       Ob = out + (size_t)b * SEQ * DIM;

    const int tid = threadIdx.x;
    const int ty  = tid >> 4;            // 0..15
    const int tx  = tid & 15;            // 0..15
    const int ty4 = ty * 4, tx4 = tx * 4, tx8 = tx * 8;

    // cooperative-load indices (transpose into smem)
    const int lr = tid >> 2;             // 0..63 (row)
    const int lk = (tid & 3) * 4;        // k base
    const int lc = (tid & 3) * 32;       // col base for V

    // ---- load Q tile transposed ----
    {
        const float* src = Qb + (size_t)(q0 + lr) * DIM;
#pragma unroll
        for (int u = 0; u < 8; u++) {
            int kk = lk + u * 16;
            float4 v = *(const float4*)(src + kk);
            Qt[(kk + 0) * 64 + lr] = v.x;
            Qt[(kk + 1) * 64 + lr] = v.y;
            Qt[(kk + 2) * 64 + lr] = v.z;
            Qt[(kk + 3) * 64 + lr] = v.w;
        }
    }

    float acc[4][8];
#pragma unroll
    for (int i = 0; i < 4; i++)
#pragma unroll
        for (int j = 0; j < 8; j++) acc[i][j] = 0.0f;
    float m_i[4], l_i[4];
#pragma unroll
    for (int i = 0; i < 4; i++) { m_i[i] = -1e30f; l_i[i] = 0.0f; }

    const float scale = 0.03125f;        // 1/sqrt(1024)

    for (int kt = 0; kt <= qt; kt++) {
        const int k0 = kt * 64;
        __syncthreads();   // protect Qt (iter 0) / Kt,Vs,Pt (later iters)

        // ---- load K tile transposed ----
        {
            const float* src = Kb + (size_t)(k0 + lr) * DIM;
#pragma unroll
            for (int u = 0; u < 8; u++) {
                int kk = lk + u * 16;
                float4 v = *(const float4*)(src + kk);
                Kt[(kk + 0) * 64 + lr] = v.x;
                Kt[(kk + 1) * 64 + lr] = v.y;
                Kt[(kk + 2) * 64 + lr] = v.z;
                Kt[(kk + 3) * 64 + lr] = v.w;
            }
        }
        // ---- load V tile row-major ----
        {
            const float* src = Vb + (size_t)(k0 + lr) * DIM + lc;
            float* dstv = Vs + lr * 128 + lc;
#pragma unroll
            for (int u = 0; u < 8; u++)
                *(float4*)(dstv + u * 4) = *(const float4*)(src + u * 4);
        }
        __syncthreads();

        // ---- S = Q K^T (4x4 per thread) ----
        float s[4][4];
#pragma unroll
        for (int i = 0; i < 4; i++)
#pragma unroll
            for (int j = 0; j < 4; j++) s[i][j] = 0.0f;

#pragma unroll 8
        for (int kk = 0; kk < 128; kk++) {
            float4 qv = *(const float4*)(Qt + kk * 64 + ty4);
            float4 kv = *(const float4*)(Kt + kk * 64 + tx4);
            float qa[4] = {qv.x, qv.y, qv.z, qv.w};
            float kb[4] = {kv.x, kv.y, kv.z, kv.w};
#pragma unroll
            for (int i = 0; i < 4; i++)
#pragma unroll
                for (int j = 0; j < 4; j++)
                    s[i][j] = fmaf(qa[i], kb[j], s[i][j]);
        }

        // ---- scale + causal mask (only on diagonal tile, k0 == q0) ----
        const bool diag = (kt == qt);
#pragma unroll
        for (int i = 0; i < 4; i++)
#pragma unroll
            for (int j = 0; j < 4; j++) {
                s[i][j] *= scale;
                if (diag && (tx4 + j) > (ty4 + i)) s[i][j] = -1e30f;
            }

        // ---- online softmax stats (rows shared by 16 tx-threads) ----
        float alpha[4];
#pragma unroll
        for (int i = 0; i < 4; i++) {
            float t = fmaxf(fmaxf(s[i][0], s[i][1]), fmaxf(s[i][2], s[i][3]));
#pragma unroll
            for (int off = 1; off < 16; off <<= 1)
                t = fmaxf(t, __shfl_xor_sync(0xffffffffu, t, off));
            float mn = fmaxf(m_i[i], t);
            alpha[i] = __expf(m_i[i] - mn);

            float r = 0.0f;
#pragma unroll
            for (int j = 0; j < 4; j++) {
                s[i][j] = __expf(s[i][j] - mn);
                r += s[i][j];
            }
#pragma unroll
            for (int off = 1; off < 16; off <<= 1)
                r += __shfl_xor_sync(0xffffffffu, r, off);

            l_i[i] = l_i[i] * alpha[i] + r;
            m_i[i] = mn;
        }

        // ---- stash P transposed: Pt[col][row] ----
#pragma unroll
        for (int i = 0; i < 4; i++)
#pragma unroll
            for (int j = 0; j < 4; j++)
                Pt[(tx4 + j) * 68 + ty4 + i] = s[i][j];
        __syncthreads();

        // ---- rescale accumulator, then O += P @ V ----
#pragma unroll
        for (int i = 0; i < 4; i++)
#pragma unroll
            for (int j = 0; j < 8; j++) acc[i][j] *= alpha[i];

#pragma unroll 4
        for (int k = 0; k < 64; k++) {
            float4 pv = *(const float4*)(Pt + k * 68 + ty4);
            float4 v0 = *(const float4*)(Vs + k * 128 + tx8);
            float4 v1 = *(const float4*)(Vs + k * 128 + tx8 + 4);
            float pp[4] = {pv.x, pv.y, pv.z, pv.w};
            float vv[8] = {v0.x, v0.y, v0.z, v0.w, v1.x, v1.y, v1.z, v1.w};
#pragma unroll
            for (int i = 0; i < 4; i++)
#pragma unroll
                for (int j = 0; j < 8; j++)
                    acc[i][j] = fmaf(pp[i], vv[j], acc[i][j]);
        }
    }

    // ---- epilogue: normalize and store ----
#pragma unroll
    for (int i = 0; i < 4; i++) {
        float inv = 1.0f / l_i[i];
        float* p = Ob + (size_t)(q0 + ty4 + i) * DIM + tx8;
        *(float4*)(p)     = make_float4(acc[i][0] * inv, acc[i][1] * inv,
                                        acc[i][2] * inv, acc[i][3] * inv);
        *(float4*)(p + 4) = make_float4(acc[i][4] * inv, acc[i][5] * inv,
                                        acc[i][6] * inv, acc[i][7] * inv);
    }
}

// ---------------------------------------------------------------------------
extern "C" void kernel_launch(void* const* d_in, const int* in_sizes, int n_in,
                              void* d_out, int out_size)
{
    const float* x  = (const float*)d_in[0];
    const float* Wq = (const float*)d_in[1];
    const float* Wk = (const float*)d_in[2];
    const float* Wv = (const float*)d_in[3];
    float* out = (float*)d_out;

    (void)in_sizes; (void)n_in; (void)out_size;

    // Stage 1: QKV projections (one pass over x per W)
    proj_kernel<<<dim3(BATCH * SEQ / 128, 3), 256>>>(x, Wq, Wk, Wv);

    // Stage 2: causal flash attention
    const size_t smem_bytes = SM_FLOATS * sizeof(float);   // 115712
    cudaFuncSetAttribute(flash_kernel,
                         cudaFuncAttributeMaxDynamicSharedMemorySize,
                         (int)smem_bytes);
    flash_kernel<<<BATCH * (SEQ / 64), 256, smem_bytes>>>(out);
}